// round 12
// baseline (speedup 1.0000x reference)
#include <cuda_runtime.h>
#include <cuda_fp16.h>
#include <math.h>

#define S   128
#define R   256
#define CM  256
#define CZ  128
#define H   8
#define CH  32
#define MROWS 32768

// ---------------- device scratch ----------------
__device__ __half g_mh[MROWS*CM];      // ln(msa), fp16
__device__ __half g_qh[MROWS*256];
__device__ __half g_kh[MROWS*256];
__device__ __half g_vh[MROWS*256];
__device__ __half g_oh[MROWS*256];     // gated attention out, fp16
__device__ float  g_g [MROWS*256];     // sigmoid gates, fp32
__device__ float  g_bias[H*R*R];       // pair bias
__device__ __half g_wt[5*256*256];     // packed transposed fp16 weights q,k,v,g,o

// smem sizes (dynamic)
#define GEMM_SMEM  (3*2*128*40*2)                               // 61440 B
#define ATTN_SMEM  ((64*40 + 2*256*40)*2 + 512 + 512 + 4*16*36*4)   // 56320 B

// prep grid split
#define PREP_PACK_BLKS 1280
#define PREP_LN_BLKS   (MROWS/8)          // 4096
#define PREP_PAIR_BLKS ((R*R)/8)          // 8192
#define PREP_TOTAL     (PREP_PACK_BLKS + PREP_LN_BLKS + PREP_PAIR_BLKS)

// ---------------- helpers ----------------
__device__ __forceinline__ unsigned sptr(const void* p) {
    return (unsigned)__cvta_generic_to_shared(p);
}
#define CP16(dst, src) asm volatile("cp.async.ca.shared.global [%0], [%1], 16;" :: "r"(dst), "l"(src) : "memory")
#define CP_COMMIT()    asm volatile("cp.async.commit_group;" ::: "memory")
#define CP_WAIT0()     asm volatile("cp.async.wait_group 0;" ::: "memory")
#define CP_WAIT1()     asm volatile("cp.async.wait_group 1;" ::: "memory")

__device__ __forceinline__ void ldsm_x4(unsigned* r, unsigned a) {
    asm volatile("ldmatrix.sync.aligned.m8n8.x4.shared.b16 {%0,%1,%2,%3}, [%4];"
        : "=r"(r[0]),"=r"(r[1]),"=r"(r[2]),"=r"(r[3]) : "r"(a));
}
__device__ __forceinline__ void ldsm_x4t(unsigned* r, unsigned a) {
    asm volatile("ldmatrix.sync.aligned.m8n8.x4.trans.shared.b16 {%0,%1,%2,%3}, [%4];"
        : "=r"(r[0]),"=r"(r[1]),"=r"(r[2]),"=r"(r[3]) : "r"(a));
}
__device__ __forceinline__ void mma16h(float* c, const unsigned* a, const unsigned* b) {
    asm volatile(
        "mma.sync.aligned.m16n8k16.row.col.f32.f16.f16.f32 "
        "{%0,%1,%2,%3}, {%4,%5,%6,%7}, {%8,%9}, {%0,%1,%2,%3};"
        : "+f"(c[0]), "+f"(c[1]), "+f"(c[2]), "+f"(c[3])
        : "r"(a[0]), "r"(a[1]), "r"(a[2]), "r"(a[3]), "r"(b[0]), "r"(b[1]));
}
__device__ __forceinline__ unsigned pk2(float a, float b) {
    __half2 h = __floats2half2_rn(a, b);
    return *reinterpret_cast<unsigned*>(&h);
}

// =======================================================================
// Fused prep: pack weights + MSA LayerNorm + pair LN/bias, one launch.
// grid = PREP_TOTAL x 256 threads, branch by block range.
// =======================================================================
__global__ void prep_kernel(const float* __restrict__ w_q, const float* __restrict__ w_k,
                            const float* __restrict__ w_v, const float* __restrict__ w_g,
                            const float* __restrict__ w_o,
                            const float* __restrict__ msa,
                            const float* __restrict__ ln_g, const float* __restrict__ ln_b,
                            const float* __restrict__ z,
                            const float* __restrict__ pg, const float* __restrict__ pb,
                            const float* __restrict__ wb, const float* __restrict__ bb) {
    int blk = blockIdx.x;
    int warp = threadIdx.x >> 5, lane = threadIdx.x & 31;

    if (blk < PREP_PACK_BLKS) {
        // ---- pack weights: fp16, transposed [n][k] ----
        int i = blk*256 + threadIdx.x;
        int m = i >> 16, rem = i & 65535;
        int n = rem & 255, k = rem >> 8;
        const float* src = (m==0)?w_q:(m==1)?w_k:(m==2)?w_v:(m==3)?w_g:w_o;
        g_wt[(size_t)m*65536 + n*256 + k] = __float2half(src[k*256 + n]);
        return;
    }
    blk -= PREP_PACK_BLKS;

    if (blk < PREP_LN_BLKS) {
        // ---- MSA LayerNorm, warp per row ----
        int row = blk*8 + warp;
        const float* xr = msa + (size_t)row*CM + lane*8;
        float4 v0 = *(const float4*)xr;
        float4 v1 = *(const float4*)(xr + 4);
        float s1 = v0.x+v0.y+v0.z+v0.w + v1.x+v1.y+v1.z+v1.w;
        float s2 = v0.x*v0.x+v0.y*v0.y+v0.z*v0.z+v0.w*v0.w
                 + v1.x*v1.x+v1.y*v1.y+v1.z*v1.z+v1.w*v1.w;
        #pragma unroll
        for (int o = 16; o; o >>= 1) {
            s1 += __shfl_xor_sync(0xffffffffu, s1, o);
            s2 += __shfl_xor_sync(0xffffffffu, s2, o);
        }
        float mu  = s1 * (1.f/CM);
        float var = s2 * (1.f/CM) - mu*mu;
        float rs  = rsqrtf(var + 1e-5f);
        float4 g0 = *(const float4*)(ln_g + lane*8);
        float4 g1 = *(const float4*)(ln_g + lane*8 + 4);
        float4 b0 = *(const float4*)(ln_b + lane*8);
        float4 b1 = *(const float4*)(ln_b + lane*8 + 4);
        uint4 o4;
        o4.x = pk2((v0.x-mu)*rs*g0.x+b0.x, (v0.y-mu)*rs*g0.y+b0.y);
        o4.y = pk2((v0.z-mu)*rs*g0.z+b0.z, (v0.w-mu)*rs*g0.w+b0.w);
        o4.z = pk2((v1.x-mu)*rs*g1.x+b1.x, (v1.y-mu)*rs*g1.y+b1.y);
        o4.w = pk2((v1.z-mu)*rs*g1.z+b1.z, (v1.w-mu)*rs*g1.w+b1.w);
        *(uint4*)(g_mh + (size_t)row*CM + lane*8) = o4;
        return;
    }
    blk -= PREP_LN_BLKS;

    // ---- pair LN + bias projection, warp per ij ----
    int ij = blk*8 + warp;
    int c0 = lane*4;
    float4 zv = *(const float4*)(z + (size_t)ij*CZ + c0);
    float s1 = zv.x+zv.y+zv.z+zv.w;
    float s2 = zv.x*zv.x+zv.y*zv.y+zv.z*zv.z+zv.w*zv.w;
    #pragma unroll
    for (int o = 16; o; o >>= 1) {
        s1 += __shfl_xor_sync(0xffffffffu, s1, o);
        s2 += __shfl_xor_sync(0xffffffffu, s2, o);
    }
    float mu  = s1 * (1.f/CZ);
    float var = s2 * (1.f/CZ) - mu*mu;
    float rs  = rsqrtf(var + 1e-5f);
    float4 gm = *(const float4*)(pg + c0);
    float4 bt = *(const float4*)(pb + c0);
    float zn0 = (zv.x-mu)*rs*gm.x + bt.x;
    float zn1 = (zv.y-mu)*rs*gm.y + bt.y;
    float zn2 = (zv.z-mu)*rs*gm.z + bt.z;
    float zn3 = (zv.w-mu)*rs*gm.w + bt.w;

    float out = 0.f;
    #pragma unroll
    for (int h = 0; h < H; ++h) {
        float p = zn0*wb[(c0+0)*H + h] + zn1*wb[(c0+1)*H + h]
                + zn2*wb[(c0+2)*H + h] + zn3*wb[(c0+3)*H + h];
        #pragma unroll
        for (int o = 16; o; o >>= 1) p += __shfl_xor_sync(0xffffffffu, p, o);
        if (lane == h) out = p;
    }
    if (lane < H) g_bias[(size_t)lane*(R*R) + ij] = out + bb[lane];
}

// =======================================================================
// fp16 GEMM with ldmatrix: C[M,N] = A[M,256] @ Bt[N,256]^T
// block 128x128, BK=32, 3-stage cp.async (dynamic smem), stride-40 pad
// EPI 0: fused QKVG epilogue (N=1024). EPI 1: +bias fp32 (N=256)
// =======================================================================
template<int EPI>
__global__ __launch_bounds__(256, 2) void gemm_h(const __half* __restrict__ A,
                                                 const __half* __restrict__ Bt,
                                                 const float* __restrict__ bias,
                                                 float* __restrict__ outF) {
    extern __shared__ __align__(16) __half smem[];
    __half* As = smem;                 // 3 stages x 128*40
    __half* Bs = smem + 3*128*40;      // 3 stages x 128*40
    const int STG = 128*40;
    const int K = 256;
    int tid = threadIdx.x, lane = tid & 31, warp = tid >> 5;
    int g = lane >> 2, tg = lane & 3;
    int wm = warp >> 1, wn = warp & 1;
    int m0 = blockIdx.y * 128, n0 = blockIdx.x * 128;
    int aRow = lane & 15, aCol = (lane >> 4) * 8;
    int bRow = (lane & 7) + ((lane >> 4) << 3), bCol = ((lane >> 3) & 1) * 8;

    float acc[2][8][4];
    #pragma unroll
    for (int mt = 0; mt < 2; ++mt)
        #pragma unroll
        for (int nt = 0; nt < 8; ++nt)
            #pragma unroll
            for (int i = 0; i < 4; ++i) acc[mt][nt][i] = 0.f;

    #define GISSUE(kt, st) {                                                    \
        const __half* Ab = A  + (size_t)m0*K + (kt)*32;                         \
        const __half* Bb = Bt + (size_t)n0*K + (kt)*32;                         \
        _Pragma("unroll")                                                       \
        for (int l = 0; l < 2; ++l) {                                           \
            int idx = l*256 + tid; int row = idx >> 2, c8 = (idx & 3)*8;        \
            CP16(sptr(As + (st)*STG + row*40 + c8), Ab + (size_t)row*K + c8);   \
            CP16(sptr(Bs + (st)*STG + row*40 + c8), Bb + (size_t)row*K + c8);   \
        }                                                                       \
        CP_COMMIT();                                                            \
    }

    GISSUE(0, 0);
    GISSUE(1, 1);
    #pragma unroll
    for (int kt = 0; kt < 8; ++kt) {
        if (kt == 7) CP_WAIT0(); else CP_WAIT1();   // tail drains fully
        __syncthreads();
        // stage (kt+2)%3 == (kt-1)%3, consumed before this barrier -> safe now
        if (kt + 2 < 8) GISSUE(kt+2, (kt+2) % 3);
        const int st = kt % 3;
        #pragma unroll
        for (int ks = 0; ks < 32; ks += 16) {
            unsigned a[2][4], b[4][4];
            #pragma unroll
            for (int mt = 0; mt < 2; ++mt)
                ldsm_x4(a[mt], sptr(As + st*STG + (wm*32 + mt*16 + aRow)*40 + ks + aCol));
            #pragma unroll
            for (int nb = 0; nb < 4; ++nb)
                ldsm_x4(b[nb], sptr(Bs + st*STG + (wn*64 + nb*16 + bRow)*40 + ks + bCol));
            #pragma unroll
            for (int mt = 0; mt < 2; ++mt)
                #pragma unroll
                for (int nb = 0; nb < 4; ++nb) {
                    mma16h(acc[mt][2*nb  ], a[mt], &b[nb][0]);
                    mma16h(acc[mt][2*nb+1], a[mt], &b[nb][2]);
                }
        }
    }
    #undef GISSUE

    #pragma unroll
    for (int mt = 0; mt < 2; ++mt) {
        int row = m0 + wm*32 + mt*16 + g;
        #pragma unroll
        for (int nt = 0; nt < 8; ++nt) {
            int col = n0 + wn*64 + nt*8 + tg*2;
            float c0 = acc[mt][nt][0], c1 = acc[mt][nt][1];
            float c2 = acc[mt][nt][2], c3 = acc[mt][nt][3];
            if (EPI == 0) {
                int chunk = col >> 8, lc = col & 255;
                if (chunk == 3) {
                    float b0 = bias[lc], b1 = bias[lc+1];
                    float v0 = 1.f/(1.f + __expf(-(c0+b0)));
                    float v1 = 1.f/(1.f + __expf(-(c1+b1)));
                    float v2 = 1.f/(1.f + __expf(-(c2+b0)));
                    float v3 = 1.f/(1.f + __expf(-(c3+b1)));
                    *(float2*)(g_g + (size_t)row*256 + lc)     = make_float2(v0, v1);
                    *(float2*)(g_g + (size_t)(row+8)*256 + lc) = make_float2(v2, v3);
                } else {
                    __half* dst = (chunk == 0) ? g_qh : (chunk == 1) ? g_kh : g_vh;
                    *(unsigned*)(dst + (size_t)row*256 + lc)     = pk2(c0, c1);
                    *(unsigned*)(dst + (size_t)(row+8)*256 + lc) = pk2(c2, c3);
                }
            } else {
                float b0 = bias[col], b1 = bias[col+1];
                *(float2*)(outF + (size_t)row*256 + col)     = make_float2(c0+b0, c1+b1);
                *(float2*)(outF + (size_t)(row+8)*256 + col) = make_float2(c2+b0, c3+b1);
            }
        }
    }
}

// =======================================================================
// Fused flash attention (R10 config — the proven one): QK^T + bias ->
// softmax -> AV -> gate. 64 q-rows per block, grid = S*H*4, 256 threads.
// Separate K and V smem buffers; all loads prefetched at block start.
// =======================================================================
__global__ __launch_bounds__(256) void attn_fused() {
    extern __shared__ __align__(16) __half smem[];
    __half* Qs = smem;                       // 64*40
    __half* Ks = smem + 64*40;               // 256*40
    __half* Vs = Ks + 256*40;                // 256*40
    float* redm = (float*)(Vs + 256*40);     // 64*2
    float* reds = redm + 128;                // 64*2
    float* Ox   = reds + 128;                // 4*16*36
    int b = blockIdx.x;
    int sh = b >> 2, m0 = (b & 3)*64;
    int s = sh >> 3, h = sh & 7;
    int tid = threadIdx.x, lane = tid & 31, warp = tid >> 5;
    int g = lane >> 2, tg = lane & 3;
    int wm = warp >> 1, wn = warp & 1;
    int aRow = lane & 15, aCol = (lane >> 4) * 8;
    int bRow = (lane & 7) + ((lane >> 4) << 3), bCol = ((lane >> 3) & 1) * 8;
    int tRow = (lane & 7) + 8*((lane >> 3) & 1), tCol = 8*(lane >> 4);

    const __half* Qp = g_qh + (size_t)(s*R + m0)*256 + h*CH;
    const __half* Kp = g_kh + (size_t)(s*R)*256 + h*CH;
    const __half* Vp = g_vh + (size_t)(s*R)*256 + h*CH;

    // prefetch group 1: Q (64x32) + K (256x32)
    {
        int row = tid >> 2, c8 = (tid & 3)*8;
        CP16(sptr(Qs + row*40 + c8), Qp + (size_t)row*256 + c8);
    }
    #pragma unroll
    for (int l = 0; l < 4; ++l) {
        int idx = l*256 + tid; int row = idx >> 2, c8 = (idx & 3)*8;
        CP16(sptr(Ks + row*40 + c8), Kp + (size_t)row*256 + c8);
    }
    CP_COMMIT();
    // prefetch group 2: V (256x32)
    #pragma unroll
    for (int l = 0; l < 4; ++l) {
        int idx = l*256 + tid; int row = idx >> 2, c8 = (idx & 3)*8;
        CP16(sptr(Vs + row*40 + c8), Vp + (size_t)row*256 + c8);
    }
    CP_COMMIT();

    CP_WAIT1();             // Q + K ready (V may still be in flight)
    __syncthreads();

    // QK^T
    float acc[16][4];
    #pragma unroll
    for (int nt = 0; nt < 16; ++nt)
        #pragma unroll
        for (int i = 0; i < 4; ++i) acc[nt][i] = 0.f;

    int rb = wm*16;
    #pragma unroll
    for (int ks = 0; ks < 32; ks += 16) {
        unsigned a[4];
        ldsm_x4(a, sptr(Qs + (rb + aRow)*40 + ks + aCol));
        #pragma unroll
        for (int nb = 0; nb < 8; ++nb) {
            unsigned bfr[4];
            ldsm_x4(bfr, sptr(Ks + (wn*128 + nb*16 + bRow)*40 + ks + bCol));
            mma16h(acc[2*nb  ], a, &bfr[0]);
            mma16h(acc[2*nb+1], a, &bfr[2]);
        }
    }

    // softmax over 256 cols
    const float sc = 0.17677669529663687f;
    int rA = rb + g, rB = rb + g + 8;
    const float* Bb = g_bias + (size_t)h*R*R + (size_t)m0*R;
    float mxA = -1e30f, mxB = -1e30f;
    #pragma unroll
    for (int nt = 0; nt < 16; ++nt) {
        int col = wn*128 + nt*8 + tg*2;
        float2 bA = *(const float2*)(Bb + (size_t)rA*R + col);
        float2 bB = *(const float2*)(Bb + (size_t)rB*R + col);
        acc[nt][0] = fmaf(acc[nt][0], sc, bA.x);
        acc[nt][1] = fmaf(acc[nt][1], sc, bA.y);
        acc[nt][2] = fmaf(acc[nt][2], sc, bB.x);
        acc[nt][3] = fmaf(acc[nt][3], sc, bB.y);
        mxA = fmaxf(mxA, fmaxf(acc[nt][0], acc[nt][1]));
        mxB = fmaxf(mxB, fmaxf(acc[nt][2], acc[nt][3]));
    }
    mxA = fmaxf(mxA, __shfl_xor_sync(0xffffffffu, mxA, 1));
    mxA = fmaxf(mxA, __shfl_xor_sync(0xffffffffu, mxA, 2));
    mxB = fmaxf(mxB, __shfl_xor_sync(0xffffffffu, mxB, 1));
    mxB = fmaxf(mxB, __shfl_xor_sync(0xffffffffu, mxB, 2));
    if (tg == 0) { redm[rA*2 + wn] = mxA; redm[rB*2 + wn] = mxB; }
    __syncthreads();
    float gA = fmaxf(redm[rA*2], redm[rA*2 + 1]);
    float gB = fmaxf(redm[rB*2], redm[rB*2 + 1]);

    float sA = 0.f, sB = 0.f;
    #pragma unroll
    for (int nt = 0; nt < 16; ++nt) {
        acc[nt][0] = __expf(acc[nt][0] - gA);
        acc[nt][1] = __expf(acc[nt][1] - gA);
        acc[nt][2] = __expf(acc[nt][2] - gB);
        acc[nt][3] = __expf(acc[nt][3] - gB);
        sA += acc[nt][0] + acc[nt][1];
        sB += acc[nt][2] + acc[nt][3];
    }
    sA += __shfl_xor_sync(0xffffffffu, sA, 1);
    sA += __shfl_xor_sync(0xffffffffu, sA, 2);
    sB += __shfl_xor_sync(0xffffffffu, sB, 1);
    sB += __shfl_xor_sync(0xffffffffu, sB, 2);
    if (tg == 0) { reds[rA*2 + wn] = sA; reds[rB*2 + wn] = sB; }
    __syncthreads();
    float iA = 1.f/(reds[rA*2] + reds[rA*2 + 1]);
    float iB = 1.f/(reds[rB*2] + reds[rB*2 + 1]);
    #pragma unroll
    for (int nt = 0; nt < 16; ++nt) {
        acc[nt][0] *= iA; acc[nt][1] *= iA;
        acc[nt][2] *= iB; acc[nt][3] *= iB;
    }

    CP_WAIT0();             // V ready (almost certainly already landed)
    __syncthreads();

    // AV: each warp contracts its 128-j half
    float oacc[4][4];
    #pragma unroll
    for (int nt = 0; nt < 4; ++nt)
        #pragma unroll
        for (int i = 0; i < 4; ++i) oacc[nt][i] = 0.f;

    #pragma unroll
    for (int t = 0; t < 8; ++t) {
        unsigned af[4];
        af[0] = pk2(acc[2*t  ][0], acc[2*t  ][1]);
        af[1] = pk2(acc[2*t  ][2], acc[2*t  ][3]);
        af[2] = pk2(acc[2*t+1][0], acc[2*t+1][1]);
        af[3] = pk2(acc[2*t+1][2], acc[2*t+1][3]);
        int j0 = wn*128 + t*16;
        #pragma unroll
        for (int nb = 0; nb < 2; ++nb) {
            unsigned bfr[4];
            ldsm_x4t(bfr, sptr(Vs + (j0 + tRow)*40 + nb*16 + tCol));
            mma16h(oacc[2*nb  ], af, &bfr[0]);
            mma16h(oacc[2*nb+1], af, &bfr[2]);
        }
    }

    if (wn == 1) {
        #pragma unroll
        for (int nt = 0; nt < 4; ++nt) {
            int col = nt*8 + tg*2;
            Ox[(wm*16 + g    )*36 + col    ] = oacc[nt][0];
            Ox[(wm*16 + g    )*36 + col + 1] = oacc[nt][1];
            Ox[(wm*16 + g + 8)*36 + col    ] = oacc[nt][2];
            Ox[(wm*16 + g + 8)*36 + col + 1] = oacc[nt][3];
        }
    }
    __syncthreads();
    if (wn == 0) {
        const float* Gp = g_g  + (size_t)(s*R + m0)*256 + h*CH;
        __half*      Op = g_oh + (size_t)(s*R + m0)*256 + h*CH;
        #pragma unroll
        for (int nt = 0; nt < 4; ++nt) {
            int col = nt*8 + tg*2;
            int r0 = wm*16 + g, r1 = r0 + 8;
            float v0 = oacc[nt][0] + Ox[r0*36 + col];
            float v1 = oacc[nt][1] + Ox[r0*36 + col + 1];
            float v2 = oacc[nt][2] + Ox[r1*36 + col];
            float v3 = oacc[nt][3] + Ox[r1*36 + col + 1];
            float2 g0 = *(const float2*)(Gp + (size_t)r0*256 + col);
            float2 g1 = *(const float2*)(Gp + (size_t)r1*256 + col);
            *(unsigned*)(Op + (size_t)r0*256 + col) = pk2(v0*g0.x, v1*g0.y);
            *(unsigned*)(Op + (size_t)r1*256 + col) = pk2(v2*g1.x, v3*g1.y);
        }
    }
}

// ---------------------------------------------------------------------------
extern "C" void kernel_launch(void* const* d_in, const int* in_sizes, int n_in,
                              void* d_out, int out_size) {
    const float* msa      = (const float*)d_in[0];
    const float* pair     = (const float*)d_in[1];
    const float* ln_msa_g = (const float*)d_in[2];
    const float* ln_msa_b = (const float*)d_in[3];
    const float* ln_pr_g  = (const float*)d_in[4];
    const float* ln_pr_b  = (const float*)d_in[5];
    const float* w_q      = (const float*)d_in[6];
    const float* w_k      = (const float*)d_in[7];
    const float* w_v      = (const float*)d_in[8];
    const float* w_g      = (const float*)d_in[9];
    const float* b_g      = (const float*)d_in[10];
    const float* w_b      = (const float*)d_in[11];
    const float* b_b      = (const float*)d_in[12];
    const float* w_o      = (const float*)d_in[13];
    const float* b_o      = (const float*)d_in[14];

    __half *pm, *po, *pw;
    cudaGetSymbolAddress((void**)&pm, g_mh);
    cudaGetSymbolAddress((void**)&po, g_oh);
    cudaGetSymbolAddress((void**)&pw, g_wt);

    cudaFuncSetAttribute(gemm_h<0>, cudaFuncAttributeMaxDynamicSharedMemorySize, GEMM_SMEM);
    cudaFuncSetAttribute(gemm_h<1>, cudaFuncAttributeMaxDynamicSharedMemorySize, GEMM_SMEM);
    cudaFuncSetAttribute(attn_fused, cudaFuncAttributeMaxDynamicSharedMemorySize, ATTN_SMEM);

    // 1. fused prep: pack weights + MSA LN + pair bias (one launch)
    prep_kernel<<<PREP_TOTAL, 256>>>(w_q, w_k, w_v, w_g, w_o,
                                     msa, ln_msa_g, ln_msa_b,
                                     pair, ln_pr_g, ln_pr_b, w_b, b_b);

    // 2. fused Q/K/V/G projection: [32768,256] x [256,1024]
    gemm_h<0><<<dim3(8, 256), 256, GEMM_SMEM>>>(pm, pw, b_g, nullptr);

    // 3. fused attention (R10 proven config)
    attn_fused<<<S*H*4, 256, ATTN_SMEM>>>();

    // 4. output projection + bias
    gemm_h<1><<<dim3(2, 256), 256, GEMM_SMEM>>>(po, pw + 4*65536, b_o, (float*)d_out);
}

// round 13
// speedup vs baseline: 1.2558x; 1.2558x over previous
#include <cuda_runtime.h>
#include <cuda_fp16.h>
#include <math.h>

#define S   128
#define R   256
#define CM  256
#define CZ  128
#define H   8
#define CH  32
#define MROWS 32768

// ---------------- device scratch ----------------
__device__ __half g_mh[MROWS*CM];      // ln(msa), fp16
__device__ __half g_qh[MROWS*256];
__device__ __half g_kh[MROWS*256];
__device__ __half g_vh[MROWS*256];
__device__ __half g_oh[MROWS*256];     // gated attention out, fp16
__device__ float  g_g [MROWS*256];     // sigmoid gates, fp32
__device__ float  g_bias[H*R*R];       // pair bias
__device__ __half g_wt[5*256*256];     // packed transposed fp16 weights q,k,v,g,o

// smem sizes (dynamic)
#define GEMM_SMEM  (3*2*128*40*2)            // 61440 B: 3 stages x (A+B) x 128x40 halves
#define ATTN_SMEM  ((64*40 + 2*256*40)*2 + 512 + 512 + 4*16*36*4)   // 56320 B

// ---------------- helpers ----------------
__device__ __forceinline__ unsigned sptr(const void* p) {
    return (unsigned)__cvta_generic_to_shared(p);
}
#define CP16(dst, src) asm volatile("cp.async.ca.shared.global [%0], [%1], 16;" :: "r"(dst), "l"(src) : "memory")
#define CP_COMMIT()    asm volatile("cp.async.commit_group;" ::: "memory")
#define CP_WAIT0()     asm volatile("cp.async.wait_group 0;" ::: "memory")
#define CP_WAIT1()     asm volatile("cp.async.wait_group 1;" ::: "memory")

__device__ __forceinline__ void ldsm_x4(unsigned* r, unsigned a) {
    asm volatile("ldmatrix.sync.aligned.m8n8.x4.shared.b16 {%0,%1,%2,%3}, [%4];"
        : "=r"(r[0]),"=r"(r[1]),"=r"(r[2]),"=r"(r[3]) : "r"(a));
}
__device__ __forceinline__ void ldsm_x4t(unsigned* r, unsigned a) {
    asm volatile("ldmatrix.sync.aligned.m8n8.x4.trans.shared.b16 {%0,%1,%2,%3}, [%4];"
        : "=r"(r[0]),"=r"(r[1]),"=r"(r[2]),"=r"(r[3]) : "r"(a));
}
__device__ __forceinline__ void mma16h(float* c, const unsigned* a, const unsigned* b) {
    asm volatile(
        "mma.sync.aligned.m16n8k16.row.col.f32.f16.f16.f32 "
        "{%0,%1,%2,%3}, {%4,%5,%6,%7}, {%8,%9}, {%0,%1,%2,%3};"
        : "+f"(c[0]), "+f"(c[1]), "+f"(c[2]), "+f"(c[3])
        : "r"(a[0]), "r"(a[1]), "r"(a[2]), "r"(a[3]), "r"(b[0]), "r"(b[1]));
}
__device__ __forceinline__ unsigned pk2(float a, float b) {
    __half2 h = __floats2half2_rn(a, b);
    return *reinterpret_cast<unsigned*>(&h);
}

// ---------------- pack weights: fp16, transposed [n][k] ----------------
__global__ void pack_w(const float* __restrict__ a0, const float* __restrict__ a1,
                       const float* __restrict__ a2, const float* __restrict__ a3,
                       const float* __restrict__ a4) {
    int i = blockIdx.x*256 + threadIdx.x;
    int m = i >> 16, rem = i & 65535;
    int n = rem & 255, k = rem >> 8;
    const float* src = (m==0)?a0:(m==1)?a1:(m==2)?a2:(m==3)?a3:a4;
    g_wt[(size_t)m*65536 + n*256 + k] = __float2half(src[k*256 + n]);
}

// ---------------- MSA LayerNorm -> fp16 ----------------
__global__ void ln_msa_kernel(const float* __restrict__ x,
                              const float* __restrict__ gamma,
                              const float* __restrict__ beta) {
    int row = blockIdx.x;
    int t = threadIdx.x;
    float v = x[(size_t)row*CM + t];
    float s1 = v, s2 = v*v;
    #pragma unroll
    for (int o = 16; o; o >>= 1) {
        s1 += __shfl_xor_sync(0xffffffffu, s1, o);
        s2 += __shfl_xor_sync(0xffffffffu, s2, o);
    }
    __shared__ float r1[8], r2[8];
    int w = t >> 5, lane = t & 31;
    if (lane == 0) { r1[w] = s1; r2[w] = s2; }
    __syncthreads();
    float ts1 = 0.f, ts2 = 0.f;
    #pragma unroll
    for (int i = 0; i < 8; ++i) { ts1 += r1[i]; ts2 += r2[i]; }
    float mu  = ts1 * (1.f/CM);
    float var = ts2 * (1.f/CM) - mu*mu;
    float rs  = rsqrtf(var + 1e-5f);
    g_mh[(size_t)row*CM + t] = __float2half((v - mu)*rs*gamma[t] + beta[t]);
}

// ---------------- pair LN + bias projection ----------------
__global__ void pair_bias_kernel(const float* __restrict__ z,
                                 const float* __restrict__ gamma,
                                 const float* __restrict__ beta,
                                 const float* __restrict__ wb,
                                 const float* __restrict__ bb) {
    int ij = blockIdx.x;
    int t  = threadIdx.x;
    float v = z[(size_t)ij*CZ + t];
    float s1 = v, s2 = v*v;
    #pragma unroll
    for (int o = 16; o; o >>= 1) {
        s1 += __shfl_xor_sync(0xffffffffu, s1, o);
        s2 += __shfl_xor_sync(0xffffffffu, s2, o);
    }
    __shared__ float r1[4], r2[4];
    int w = t >> 5, lane = t & 31;
    if (lane == 0) { r1[w] = s1; r2[w] = s2; }
    __syncthreads();
    float ts1 = r1[0]+r1[1]+r1[2]+r1[3];
    float ts2 = r2[0]+r2[1]+r2[2]+r2[3];
    float mu  = ts1 * (1.f/CZ);
    float var = ts2 * (1.f/CZ) - mu*mu;
    float rs  = rsqrtf(var + 1e-5f);
    float zn  = (v - mu)*rs*gamma[t] + beta[t];

    __shared__ float part[4][8];
    #pragma unroll
    for (int h = 0; h < H; ++h) {
        float p = zn * wb[t*H + h];
        #pragma unroll
        for (int o = 16; o; o >>= 1) p += __shfl_xor_sync(0xffffffffu, p, o);
        if (lane == 0) part[w][h] = p;
    }
    __syncthreads();
    if (t < H) {
        float sum = part[0][t] + part[1][t] + part[2][t] + part[3][t] + bb[t];
        g_bias[(size_t)t*(R*R) + ij] = sum;
    }
}

// =======================================================================
// fp16 GEMM with ldmatrix: C[M,N] = A[M,256] @ Bt[N,256]^T
// block 128x128, BK=32, 3-stage cp.async (dynamic smem), stride-40 pad
// 8 warps (4x2), warp 32x64. Natural register allocation (2 CTAs/SM).
// EPI 0: fused QKVG epilogue (N=1024). EPI 1: +bias fp32 (N=256)
// =======================================================================
template<int EPI>
__global__ __launch_bounds__(256) void gemm_h(const __half* __restrict__ A,
                                              const __half* __restrict__ Bt,
                                              const float* __restrict__ bias,
                                              float* __restrict__ outF) {
    extern __shared__ __align__(16) __half smem[];
    __half* As = smem;                 // 3 stages x 128*40
    __half* Bs = smem + 3*128*40;      // 3 stages x 128*40
    const int STG = 128*40;
    const int K = 256;
    int tid = threadIdx.x, lane = tid & 31, warp = tid >> 5;
    int g = lane >> 2, tg = lane & 3;
    int wm = warp >> 1, wn = warp & 1;
    int m0 = blockIdx.y * 128, n0 = blockIdx.x * 128;
    int aRow = lane & 15, aCol = (lane >> 4) * 8;
    int bRow = (lane & 7) + ((lane >> 4) << 3), bCol = ((lane >> 3) & 1) * 8;

    float acc[2][8][4];
    #pragma unroll
    for (int mt = 0; mt < 2; ++mt)
        #pragma unroll
        for (int nt = 0; nt < 8; ++nt)
            #pragma unroll
            for (int i = 0; i < 4; ++i) acc[mt][nt][i] = 0.f;

    #define GISSUE(kt, st) {                                                    \
        const __half* Ab = A  + (size_t)m0*K + (kt)*32;                         \
        const __half* Bb = Bt + (size_t)n0*K + (kt)*32;                         \
        _Pragma("unroll")                                                       \
        for (int l = 0; l < 2; ++l) {                                           \
            int idx = l*256 + tid; int row = idx >> 2, c8 = (idx & 3)*8;        \
            CP16(sptr(As + (st)*STG + row*40 + c8), Ab + (size_t)row*K + c8);   \
            CP16(sptr(Bs + (st)*STG + row*40 + c8), Bb + (size_t)row*K + c8);   \
        }                                                                       \
        CP_COMMIT();                                                            \
    }

    GISSUE(0, 0);
    GISSUE(1, 1);
    #pragma unroll
    for (int kt = 0; kt < 8; ++kt) {
        // Tail: at the last iteration the final group must be fully drained.
        if (kt == 7) CP_WAIT0(); else CP_WAIT1();
        __syncthreads();
        const int st = kt % 3;
        #pragma unroll
        for (int ks = 0; ks < 32; ks += 16) {
            unsigned a[2][4], b[4][4];
            #pragma unroll
            for (int mt = 0; mt < 2; ++mt)
                ldsm_x4(a[mt], sptr(As + st*STG + (wm*32 + mt*16 + aRow)*40 + ks + aCol));
            #pragma unroll
            for (int nb = 0; nb < 4; ++nb)
                ldsm_x4(b[nb], sptr(Bs + st*STG + (wn*64 + nb*16 + bRow)*40 + ks + bCol));
            #pragma unroll
            for (int mt = 0; mt < 2; ++mt)
                #pragma unroll
                for (int nb = 0; nb < 4; ++nb) {
                    mma16h(acc[mt][2*nb  ], a[mt], &b[nb][0]);
                    mma16h(acc[mt][2*nb+1], a[mt], &b[nb][2]);
                }
        }
        if (kt + 2 < 8) {
            GISSUE(kt+2, (kt+2) % 3);
        }
    }
    #undef GISSUE

    #pragma unroll
    for (int mt = 0; mt < 2; ++mt) {
        int row = m0 + wm*32 + mt*16 + g;
        #pragma unroll
        for (int nt = 0; nt < 8; ++nt) {
            int col = n0 + wn*64 + nt*8 + tg*2;
            float c0 = acc[mt][nt][0], c1 = acc[mt][nt][1];
            float c2 = acc[mt][nt][2], c3 = acc[mt][nt][3];
            if (EPI == 0) {
                int chunk = col >> 8, lc = col & 255;
                if (chunk == 3) {
                    float b0 = bias[lc], b1 = bias[lc+1];
                    float v0 = 1.f/(1.f + __expf(-(c0+b0)));
                    float v1 = 1.f/(1.f + __expf(-(c1+b1)));
                    float v2 = 1.f/(1.f + __expf(-(c2+b0)));
                    float v3 = 1.f/(1.f + __expf(-(c3+b1)));
                    *(float2*)(g_g + (size_t)row*256 + lc)     = make_float2(v0, v1);
                    *(float2*)(g_g + (size_t)(row+8)*256 + lc) = make_float2(v2, v3);
                } else {
                    __half* dst = (chunk == 0) ? g_qh : (chunk == 1) ? g_kh : g_vh;
                    *(unsigned*)(dst + (size_t)row*256 + lc)     = pk2(c0, c1);
                    *(unsigned*)(dst + (size_t)(row+8)*256 + lc) = pk2(c2, c3);
                }
            } else {
                float b0 = bias[col], b1 = bias[col+1];
                *(float2*)(outF + (size_t)row*256 + col)     = make_float2(c0+b0, c1+b1);
                *(float2*)(outF + (size_t)(row+8)*256 + col) = make_float2(c2+b0, c3+b1);
            }
        }
    }
}

// =======================================================================
// Fused flash attention (dynamic smem): QK^T + bias -> softmax -> AV -> gate
// 64 q-rows per block, grid = S*H*4, 256 threads (4 wm x 2 wn)
// Separate K and V buffers; ALL loads prefetched at block start.
// =======================================================================
__global__ __launch_bounds__(256) void attn_fused() {
    extern __shared__ __align__(16) __half smem[];
    __half* Qs = smem;                       // 64*40
    __half* Ks = smem + 64*40;               // 256*40
    __half* Vs = Ks + 256*40;                // 256*40
    float* redm = (float*)(Vs + 256*40);     // 64*2
    float* reds = redm + 128;                // 64*2
    float* Ox   = reds + 128;                // 4*16*36
    int b = blockIdx.x;
    int sh = b >> 2, m0 = (b & 3)*64;
    int s = sh >> 3, h = sh & 7;
    int tid = threadIdx.x, lane = tid & 31, warp = tid >> 5;
    int g = lane >> 2, tg = lane & 3;
    int wm = warp >> 1, wn = warp & 1;
    int aRow = lane & 15, aCol = (lane >> 4) * 8;
    int bRow = (lane & 7) + ((lane >> 4) << 3), bCol = ((lane >> 3) & 1) * 8;
    int tRow = (lane & 7) + 8*((lane >> 3) & 1), tCol = 8*(lane >> 4);

    const __half* Qp = g_qh + (size_t)(s*R + m0)*256 + h*CH;
    const __half* Kp = g_kh + (size_t)(s*R)*256 + h*CH;
    const __half* Vp = g_vh + (size_t)(s*R)*256 + h*CH;

    // prefetch group 1: Q (64x32) + K (256x32)
    {
        int row = tid >> 2, c8 = (tid & 3)*8;
        CP16(sptr(Qs + row*40 + c8), Qp + (size_t)row*256 + c8);
    }
    #pragma unroll
    for (int l = 0; l < 4; ++l) {
        int idx = l*256 + tid; int row = idx >> 2, c8 = (idx & 3)*8;
        CP16(sptr(Ks + row*40 + c8), Kp + (size_t)row*256 + c8);
    }
    CP_COMMIT();
    // prefetch group 2: V (256x32)
    #pragma unroll
    for (int l = 0; l < 4; ++l) {
        int idx = l*256 + tid; int row = idx >> 2, c8 = (idx & 3)*8;
        CP16(sptr(Vs + row*40 + c8), Vp + (size_t)row*256 + c8);
    }
    CP_COMMIT();

    CP_WAIT1();             // Q + K ready (V may still be in flight)
    __syncthreads();

    // QK^T
    float acc[16][4];
    #pragma unroll
    for (int nt = 0; nt < 16; ++nt)
        #pragma unroll
        for (int i = 0; i < 4; ++i) acc[nt][i] = 0.f;

    int rb = wm*16;
    #pragma unroll
    for (int ks = 0; ks < 32; ks += 16) {
        unsigned a[4];
        ldsm_x4(a, sptr(Qs + (rb + aRow)*40 + ks + aCol));
        #pragma unroll
        for (int nb = 0; nb < 8; ++nb) {
            unsigned bfr[4];
            ldsm_x4(bfr, sptr(Ks + (wn*128 + nb*16 + bRow)*40 + ks + bCol));
            mma16h(acc[2*nb  ], a, &bfr[0]);
            mma16h(acc[2*nb+1], a, &bfr[2]);
        }
    }

    // softmax over 256 cols
    const float sc = 0.17677669529663687f;
    int rA = rb + g, rB = rb + g + 8;
    const float* Bb = g_bias + (size_t)h*R*R + (size_t)m0*R;
    float mxA = -1e30f, mxB = -1e30f;
    #pragma unroll
    for (int nt = 0; nt < 16; ++nt) {
        int col = wn*128 + nt*8 + tg*2;
        float2 bA = *(const float2*)(Bb + (size_t)rA*R + col);
        float2 bB = *(const float2*)(Bb + (size_t)rB*R + col);
        acc[nt][0] = fmaf(acc[nt][0], sc, bA.x);
        acc[nt][1] = fmaf(acc[nt][1], sc, bA.y);
        acc[nt][2] = fmaf(acc[nt][2], sc, bB.x);
        acc[nt][3] = fmaf(acc[nt][3], sc, bB.y);
        mxA = fmaxf(mxA, fmaxf(acc[nt][0], acc[nt][1]));
        mxB = fmaxf(mxB, fmaxf(acc[nt][2], acc[nt][3]));
    }
    mxA = fmaxf(mxA, __shfl_xor_sync(0xffffffffu, mxA, 1));
    mxA = fmaxf(mxA, __shfl_xor_sync(0xffffffffu, mxA, 2));
    mxB = fmaxf(mxB, __shfl_xor_sync(0xffffffffu, mxB, 1));
    mxB = fmaxf(mxB, __shfl_xor_sync(0xffffffffu, mxB, 2));
    if (tg == 0) { redm[rA*2 + wn] = mxA; redm[rB*2 + wn] = mxB; }
    __syncthreads();
    float gA = fmaxf(redm[rA*2], redm[rA*2 + 1]);
    float gB = fmaxf(redm[rB*2], redm[rB*2 + 1]);

    float sA = 0.f, sB = 0.f;
    #pragma unroll
    for (int nt = 0; nt < 16; ++nt) {
        acc[nt][0] = __expf(acc[nt][0] - gA);
        acc[nt][1] = __expf(acc[nt][1] - gA);
        acc[nt][2] = __expf(acc[nt][2] - gB);
        acc[nt][3] = __expf(acc[nt][3] - gB);
        sA += acc[nt][0] + acc[nt][1];
        sB += acc[nt][2] + acc[nt][3];
    }
    sA += __shfl_xor_sync(0xffffffffu, sA, 1);
    sA += __shfl_xor_sync(0xffffffffu, sA, 2);
    sB += __shfl_xor_sync(0xffffffffu, sB, 1);
    sB += __shfl_xor_sync(0xffffffffu, sB, 2);
    if (tg == 0) { reds[rA*2 + wn] = sA; reds[rB*2 + wn] = sB; }
    __syncthreads();
    float iA = 1.f/(reds[rA*2] + reds[rA*2 + 1]);
    float iB = 1.f/(reds[rB*2] + reds[rB*2 + 1]);
    #pragma unroll
    for (int nt = 0; nt < 16; ++nt) {
        acc[nt][0] *= iA; acc[nt][1] *= iA;
        acc[nt][2] *= iB; acc[nt][3] *= iB;
    }

    CP_WAIT0();             // V ready (almost certainly already landed)
    __syncthreads();

    // AV: each warp contracts its 128-j half
    float oacc[4][4];
    #pragma unroll
    for (int nt = 0; nt < 4; ++nt)
        #pragma unroll
        for (int i = 0; i < 4; ++i) oacc[nt][i] = 0.f;

    #pragma unroll
    for (int t = 0; t < 8; ++t) {
        unsigned af[4];
        af[0] = pk2(acc[2*t  ][0], acc[2*t  ][1]);
        af[1] = pk2(acc[2*t  ][2], acc[2*t  ][3]);
        af[2] = pk2(acc[2*t+1][0], acc[2*t+1][1]);
        af[3] = pk2(acc[2*t+1][2], acc[2*t+1][3]);
        int j0 = wn*128 + t*16;
        #pragma unroll
        for (int nb = 0; nb < 2; ++nb) {
            unsigned bfr[4];
            ldsm_x4t(bfr, sptr(Vs + (j0 + tRow)*40 + nb*16 + tCol));
            mma16h(oacc[2*nb  ], af, &bfr[0]);
            mma16h(oacc[2*nb+1], af, &bfr[2]);
        }
    }

    if (wn == 1) {
        #pragma unroll
        for (int nt = 0; nt < 4; ++nt) {
            int col = nt*8 + tg*2;
            Ox[(wm*16 + g    )*36 + col    ] = oacc[nt][0];
            Ox[(wm*16 + g    )*36 + col + 1] = oacc[nt][1];
            Ox[(wm*16 + g + 8)*36 + col    ] = oacc[nt][2];
            Ox[(wm*16 + g + 8)*36 + col + 1] = oacc[nt][3];
        }
    }
    __syncthreads();
    if (wn == 0) {
        const float* Gp = g_g  + (size_t)(s*R + m0)*256 + h*CH;
        __half*      Op = g_oh + (size_t)(s*R + m0)*256 + h*CH;
        #pragma unroll
        for (int nt = 0; nt < 4; ++nt) {
            int col = nt*8 + tg*2;
            int r0 = wm*16 + g, r1 = r0 + 8;
            float v0 = oacc[nt][0] + Ox[r0*36 + col];
            float v1 = oacc[nt][1] + Ox[r0*36 + col + 1];
            float v2 = oacc[nt][2] + Ox[r1*36 + col];
            float v3 = oacc[nt][3] + Ox[r1*36 + col + 1];
            float2 g0 = *(const float2*)(Gp + (size_t)r0*256 + col);
            float2 g1 = *(const float2*)(Gp + (size_t)r1*256 + col);
            *(unsigned*)(Op + (size_t)r0*256 + col) = pk2(v0*g0.x, v1*g0.y);
            *(unsigned*)(Op + (size_t)r1*256 + col) = pk2(v2*g1.x, v3*g1.y);
        }
    }
}

// ---------------------------------------------------------------------------
extern "C" void kernel_launch(void* const* d_in, const int* in_sizes, int n_in,
                              void* d_out, int out_size) {
    const float* msa      = (const float*)d_in[0];
    const float* pair     = (const float*)d_in[1];
    const float* ln_msa_g = (const float*)d_in[2];
    const float* ln_msa_b = (const float*)d_in[3];
    const float* ln_pr_g  = (const float*)d_in[4];
    const float* ln_pr_b  = (const float*)d_in[5];
    const float* w_q      = (const float*)d_in[6];
    const float* w_k      = (const float*)d_in[7];
    const float* w_v      = (const float*)d_in[8];
    const float* w_g      = (const float*)d_in[9];
    const float* b_g      = (const float*)d_in[10];
    const float* w_b      = (const float*)d_in[11];
    const float* b_b      = (const float*)d_in[12];
    const float* w_o      = (const float*)d_in[13];
    const float* b_o      = (const float*)d_in[14];

    __half *pm, *po, *pw;
    cudaGetSymbolAddress((void**)&pm, g_mh);
    cudaGetSymbolAddress((void**)&po, g_oh);
    cudaGetSymbolAddress((void**)&pw, g_wt);

    cudaFuncSetAttribute(gemm_h<0>, cudaFuncAttributeMaxDynamicSharedMemorySize, GEMM_SMEM);
    cudaFuncSetAttribute(gemm_h<1>, cudaFuncAttributeMaxDynamicSharedMemorySize, GEMM_SMEM);
    cudaFuncSetAttribute(attn_fused, cudaFuncAttributeMaxDynamicSharedMemorySize, ATTN_SMEM);

    // 1. prep: weights fp16+transpose, LN, pair bias
    pack_w<<<1280, 256>>>(w_q, w_k, w_v, w_g, w_o);
    ln_msa_kernel<<<MROWS, 256>>>(msa, ln_msa_g, ln_msa_b);
    pair_bias_kernel<<<R*R, 128>>>(pair, ln_pr_g, ln_pr_b, w_b, b_b);

    // 2. fused Q/K/V/G projection: [32768,256] x [256,1024]
    gemm_h<0><<<dim3(8, 256), 256, GEMM_SMEM>>>(pm, pw, b_g, nullptr);

    // 3. fused attention
    attn_fused<<<S*H*4, 256, ATTN_SMEM>>>();

    // 4. output projection + bias
    gemm_h<1><<<dim3(2, 256), 256, GEMM_SMEM>>>(po, pw + 4*65536, b_o, (float*)d_out);
}